// round 3
// baseline (speedup 1.0000x reference)
#include <cuda_runtime.h>
#include <math.h>

#define BB 8
#define NN 2048
#define DD 128
#define TI 64
#define TJ 128

typedef unsigned long long u64;

// -------- scratch (static device globals; no allocation) --------
__device__ float g_Wh[BB * NN * DD];   // 8 MB
__device__ float g_e1[BB * NN];
__device__ float g_e2[BB * NN];
__device__ float g_pooled[BB * DD];

// -------- packed f32x2 helpers (Blackwell fp32 pipe at 2x) --------
__device__ __forceinline__ u64 pack2(float x, float y) {
    u64 r; asm("mov.b64 %0, {%1,%2};" : "=l"(r) : "f"(x), "f"(y)); return r;
}
__device__ __forceinline__ u64 fma2(u64 a, u64 b, u64 c) {
    u64 d; asm("fma.rn.f32x2 %0, %1, %2, %3;" : "=l"(d) : "l"(a), "l"(b), "l"(c)); return d;
}
__device__ __forceinline__ float2 unpack2(u64 v) {
    float2 r; asm("mov.b64 {%0,%1}, %2;" : "=f"(r.x), "=f"(r.y) : "l"(v)); return r;
}
__device__ __forceinline__ float lrelu(float x) { return x >= 0.f ? x : 0.02f * x; }

// ============================================================
// Kernel 0: init pooled to -inf (graph replays re-run this)
// ============================================================
__global__ void init_pooled_kernel() {
    int t = blockIdx.x * blockDim.x + threadIdx.x;
    if (t < BB * DD) g_pooled[t] = __int_as_float(0xff800000); // -inf
}

// ============================================================
// Kernel 1: fc1 + layernorm + lrelu + Wg GEMM + bias + e1/e2
//   grid: 256 blocks x 256 threads, 64 nodes/block
// ============================================================
__global__ void __launch_bounds__(256, 2) fc_kernel(
    const float* __restrict__ h, const float* __restrict__ W1, const float* __restrict__ b1,
    const float* __restrict__ Wg, const float* __restrict__ bg,
    const float* __restrict__ a1, const float* __restrict__ a2)
{
    extern __shared__ float sm[];
    float* Wgs = sm;                    // [128][132] transposed, padded
    float* x_s = Wgs + 128 * 132;       // [64][128]
    float* W1t = x_s + TI * DD;         // [10][128] transposed
    float* h_s = W1t + 1280;            // [64][10]
    float* b1s = h_s + TI * 10;
    float* bgs = b1s + 128;
    float* a1s = bgs + 128;
    float* a2s = a1s + 128;

    int tid = threadIdx.x;
    int warp = tid >> 5, lane = tid & 31;
    int node0 = blockIdx.x * TI;        // global flat node (b*N+n)

    // ---- cooperative loads ----
    #pragma unroll
    for (int it = 0; it < 64; it++) {   // Wg[d][k] -> Wgs[k][d]
        int idx = it * 256 + tid;
        Wgs[(idx & 127) * 132 + (idx >> 7)] = Wg[idx];
    }
    for (int idx = tid; idx < 1280; idx += 256)  // W1[d][f] -> W1t[f][d]
        W1t[(idx % 10) * 128 + (idx / 10)] = W1[idx];
    for (int idx = tid; idx < TI * 10; idx += 256)
        h_s[idx] = h[node0 * 10 + idx];
    if (tid < 128) { b1s[tid] = b1[tid]; bgs[tid] = bg[tid]; a1s[tid] = a1[tid]; a2s[tid] = a2[tid]; }
    __syncthreads();

    // ---- phase A: x = lrelu(LN(h @ W1.T + b1)), warp per node ----
    for (int it = 0; it < 8; it++) {
        int nl = it * 8 + warp;
        float xv[4];
        #pragma unroll
        for (int c = 0; c < 4; c++) xv[c] = b1s[4 * lane + c];
        #pragma unroll
        for (int f = 0; f < 10; f++) {
            float hf = h_s[nl * 10 + f];
            #pragma unroll
            for (int c = 0; c < 4; c++) xv[c] += hf * W1t[f * 128 + 4 * lane + c];
        }
        float s  = xv[0] + xv[1] + xv[2] + xv[3];
        float ss = xv[0]*xv[0] + xv[1]*xv[1] + xv[2]*xv[2] + xv[3]*xv[3];
        #pragma unroll
        for (int o = 16; o > 0; o >>= 1) {
            s  += __shfl_xor_sync(0xffffffffu, s, o);
            ss += __shfl_xor_sync(0xffffffffu, ss, o);
        }
        float m   = s * (1.f / 128.f);
        float var = ss * (1.f / 128.f) - m * m;
        float inv = rsqrtf(var + 1e-5f);
        #pragma unroll
        for (int c = 0; c < 4; c++)
            x_s[nl * DD + 4 * lane + c] = lrelu((xv[c] - m) * inv);
    }
    __syncthreads();

    // ---- GEMM: Wh = x @ Wg.T  (64x128 @ 128x128), FFMA2 ----
    u64 acc[8][2];
    #pragma unroll
    for (int r = 0; r < 8; r++) { acc[r][0] = 0ull; acc[r][1] = 0ull; }
    for (int kb = 0; kb < 32; kb++) {
        ulonglong2 v[4];
        #pragma unroll
        for (int q = 0; q < 4; q++)
            v[q] = *(const ulonglong2*)(Wgs + (4 * kb + q) * 132 + 4 * lane);
        #pragma unroll
        for (int r = 0; r < 8; r++) {
            float4 w4 = *(const float4*)(x_s + (warp * 8 + r) * DD + 4 * kb);
            u64 w;
            w = pack2(w4.x, w4.x); acc[r][0] = fma2(w, v[0].x, acc[r][0]); acc[r][1] = fma2(w, v[0].y, acc[r][1]);
            w = pack2(w4.y, w4.y); acc[r][0] = fma2(w, v[1].x, acc[r][0]); acc[r][1] = fma2(w, v[1].y, acc[r][1]);
            w = pack2(w4.z, w4.z); acc[r][0] = fma2(w, v[2].x, acc[r][0]); acc[r][1] = fma2(w, v[2].y, acc[r][1]);
            w = pack2(w4.w, w4.w); acc[r][0] = fma2(w, v[3].x, acc[r][0]); acc[r][1] = fma2(w, v[3].y, acc[r][1]);
        }
    }

    // ---- epilogue: +bg, store Wh, e1/e2 dots ----
    #pragma unroll
    for (int r = 0; r < 8; r++) {
        int gn = node0 + warp * 8 + r;
        float2 p0 = unpack2(acc[r][0]);
        float2 p1 = unpack2(acc[r][1]);
        float w0 = p0.x + bgs[4 * lane + 0];
        float w1 = p0.y + bgs[4 * lane + 1];
        float w2 = p1.x + bgs[4 * lane + 2];
        float w3 = p1.y + bgs[4 * lane + 3];
        *(float4*)(g_Wh + (size_t)gn * DD + 4 * lane) = make_float4(w0, w1, w2, w3);
        float d1 = w0 * a1s[4*lane] + w1 * a1s[4*lane+1] + w2 * a1s[4*lane+2] + w3 * a1s[4*lane+3];
        float d2 = w0 * a2s[4*lane] + w1 * a2s[4*lane+1] + w2 * a2s[4*lane+2] + w3 * a2s[4*lane+3];
        #pragma unroll
        for (int o = 16; o > 0; o >>= 1) {
            d1 += __shfl_xor_sync(0xffffffffu, d1, o);
            d2 += __shfl_xor_sync(0xffffffffu, d2, o);
        }
        if (lane == 0) { g_e1[gn] = d1; g_e2[gn] = d2; }
    }
}

// ============================================================
// Kernel 2: attention + LN + lrelu + max-pool (fused epilogue)
//   grid: (32, 8) x 256 threads. Block: 64 i-rows, loop 128-j tiles.
//   No max-subtraction needed (e1+e2 bounded ~ +-10 -> exp safe in fp32).
// ============================================================
__global__ void __launch_bounds__(256, 2) attn_kernel(const int* __restrict__ adj)
{
    extern __shared__ float sm[];
    float* Wh_s = sm;                // [128][128]
    float* w_s  = Wh_s + TJ * DD;    // [64][128]
    float* e2_s = w_s + TI * TJ;     // [128]

    int tid = threadIdx.x;
    int warp = tid >> 5, lane = tid & 31;
    int b  = blockIdx.y;
    int i0 = blockIdx.x * TI;

    float e1r[8];
    #pragma unroll
    for (int r = 0; r < 8; r++) e1r[r] = g_e1[b * NN + i0 + warp * 8 + r];

    u64 acc[8][2];
    #pragma unroll
    for (int r = 0; r < 8; r++) { acc[r][0] = 0ull; acc[r][1] = 0ull; }
    float z[8];
    #pragma unroll
    for (int r = 0; r < 8; r++) z[r] = 0.f;

    const float* Whb = g_Wh + (size_t)b * NN * DD;
    const int*  adjb = adj + (size_t)b * NN * NN;

    for (int tile = 0; tile < NN / TJ; tile++) {
        int j0 = tile * TJ;
        if (tid < TJ) e2_s[tid] = g_e2[b * NN + j0 + tid];
        {
            const float4* src = (const float4*)(Whb + (size_t)j0 * DD);
            float4* dst = (float4*)Wh_s;
            #pragma unroll
            for (int it = 0; it < 16; it++) dst[it * 256 + tid] = src[it * 256 + tid];
        }

        // ---- adj prefetch BEFORE barrier: LDG.128 per row, compress to 4-bit mask ----
        unsigned am[8];
        #pragma unroll
        for (int r = 0; r < 8; r++) {
            const int* arow = adjb + (size_t)(i0 + warp * 8 + r) * NN + j0;
            int4 a4 = *(const int4*)(arow + 4 * lane);
            am[r] = (a4.x != 0 ? 1u : 0u) | (a4.y != 0 ? 2u : 0u)
                  | (a4.z != 0 ? 4u : 0u) | (a4.w != 0 ? 8u : 0u);
        }
        __syncthreads();

        // ---- w-gen: w = adj ? exp(lrelu(e1_i + e2_j)) : 0 ; accumulate Z ----
        float4 e2v = *(const float4*)(e2_s + 4 * lane);
        #pragma unroll
        for (int r = 0; r < 8; r++) {
            float w0 = (am[r] & 1u) ? __expf(lrelu(e1r[r] + e2v.x)) : 0.f;
            float w1 = (am[r] & 2u) ? __expf(lrelu(e1r[r] + e2v.y)) : 0.f;
            float w2 = (am[r] & 4u) ? __expf(lrelu(e1r[r] + e2v.z)) : 0.f;
            float w3 = (am[r] & 8u) ? __expf(lrelu(e1r[r] + e2v.w)) : 0.f;
            *(float4*)(w_s + (warp * 8 + r) * TJ + 4 * lane) = make_float4(w0, w1, w2, w3);
            float zp = w0 + w1 + w2 + w3;
            #pragma unroll
            for (int o = 16; o > 0; o >>= 1) zp += __shfl_xor_sync(0xffffffffu, zp, o);
            z[r] += zp;
        }
        __syncwarp();   // warp reads only its own w_s rows

        // ---- main FFMA2 accumulate: acc[r] += w * Wh ----
        for (int jb = 0; jb < TJ / 4; jb++) {
            ulonglong2 v[4];
            #pragma unroll
            for (int q = 0; q < 4; q++)
                v[q] = *(const ulonglong2*)(Wh_s + (4 * jb + q) * DD + 4 * lane);
            #pragma unroll
            for (int r = 0; r < 8; r++) {
                float4 w4 = *(const float4*)(w_s + (warp * 8 + r) * TJ + 4 * jb);
                u64 w;
                w = pack2(w4.x, w4.x); acc[r][0] = fma2(w, v[0].x, acc[r][0]); acc[r][1] = fma2(w, v[0].y, acc[r][1]);
                w = pack2(w4.y, w4.y); acc[r][0] = fma2(w, v[1].x, acc[r][0]); acc[r][1] = fma2(w, v[1].y, acc[r][1]);
                w = pack2(w4.z, w4.z); acc[r][0] = fma2(w, v[2].x, acc[r][0]); acc[r][1] = fma2(w, v[2].y, acc[r][1]);
                w = pack2(w4.w, w4.w); acc[r][0] = fma2(w, v[3].x, acc[r][0]); acc[r][1] = fma2(w, v[3].y, acc[r][1]);
            }
        }
        __syncthreads();
    }

    // ---- epilogue: /Z, layernorm, lrelu, running max ----
    float lmax[4] = {-1e30f, -1e30f, -1e30f, -1e30f};
    #pragma unroll
    for (int r = 0; r < 8; r++) {
        float invz = 1.f / z[r];
        float2 p0 = unpack2(acc[r][0]);
        float2 p1 = unpack2(acc[r][1]);
        float x0 = p0.x * invz, x1 = p0.y * invz, x2 = p1.x * invz, x3 = p1.y * invz;
        float s  = x0 + x1 + x2 + x3;
        float ss = x0*x0 + x1*x1 + x2*x2 + x3*x3;
        #pragma unroll
        for (int o = 16; o > 0; o >>= 1) {
            s  += __shfl_xor_sync(0xffffffffu, s, o);
            ss += __shfl_xor_sync(0xffffffffu, ss, o);
        }
        float m   = s * (1.f / 128.f);
        float var = ss * (1.f / 128.f) - m * m;
        float inv = rsqrtf(var + 1e-5f);
        lmax[0] = fmaxf(lmax[0], lrelu((x0 - m) * inv));
        lmax[1] = fmaxf(lmax[1], lrelu((x1 - m) * inv));
        lmax[2] = fmaxf(lmax[2], lrelu((x2 - m) * inv));
        lmax[3] = fmaxf(lmax[3], lrelu((x3 - m) * inv));
    }
    // block-level max reduce then one atomic per d
    float* red = w_s;   // reuse (post-loop barrier already passed)
    #pragma unroll
    for (int c = 0; c < 4; c++) red[warp * DD + 4 * lane + c] = lmax[c];
    __syncthreads();
    if (tid < DD) {
        float v = red[tid];
        #pragma unroll
        for (int w = 1; w < 8; w++) v = fmaxf(v, red[w * DD + tid]);
        if (v >= 0.f) atomicMax((int*)&g_pooled[b * DD + tid], __float_as_int(v));
        else          atomicMin((unsigned int*)&g_pooled[b * DD + tid], __float_as_uint(v));
    }
}

// ============================================================
// Kernel 3: pooled @ W2.T + b2, log_softmax -> out [8,2]
// ============================================================
__global__ void final_kernel(const float* __restrict__ W2, const float* __restrict__ b2,
                             float* __restrict__ out)
{
    int t = threadIdx.x;
    if (t < BB) {
        float o0 = b2[0], o1 = b2[1];
        for (int d = 0; d < DD; d++) {
            float p = g_pooled[t * DD + d];
            o0 += p * W2[d];
            o1 += p * W2[DD + d];
        }
        float m = fmaxf(o0, o1);
        float l = m + logf(expf(o0 - m) + expf(o1 - m));
        out[2 * t + 0] = o0 - l;
        out[2 * t + 1] = o1 - l;
    }
}

// ============================================================
extern "C" void kernel_launch(void* const* d_in, const int* in_sizes, int n_in,
                              void* d_out, int out_size)
{
    const float* h  = (const float*)d_in[0];
    const int*   adj = (const int*)d_in[1];
    const float* W1 = (const float*)d_in[2];
    const float* b1 = (const float*)d_in[3];
    const float* Wg = (const float*)d_in[4];
    const float* bg = (const float*)d_in[5];
    const float* a1 = (const float*)d_in[6];
    const float* a2 = (const float*)d_in[7];
    const float* W2 = (const float*)d_in[8];
    const float* b2 = (const float*)d_in[9];
    float* out = (float*)d_out;

    int smem_fc = (128 * 132 + TI * DD + 1280 + TI * 10 + 4 * 128) * 4;  // ~110 KB
    int smem_at = (TJ * DD + TI * TJ + TJ) * 4;                          // ~97 KB
    cudaFuncSetAttribute(fc_kernel,   cudaFuncAttributeMaxDynamicSharedMemorySize, smem_fc);
    cudaFuncSetAttribute(attn_kernel, cudaFuncAttributeMaxDynamicSharedMemorySize, smem_at);

    init_pooled_kernel<<<1, 1024>>>();
    fc_kernel<<<BB * NN / TI, 256, smem_fc>>>(h, W1, b1, Wg, bg, a1, a2);
    attn_kernel<<<dim3(NN / TI, BB), 256, smem_at>>>(adj);
    final_kernel<<<1, 32>>>(W2, b2, out);
}

// round 5
// speedup vs baseline: 1.1822x; 1.1822x over previous
#include <cuda_runtime.h>
#include <math.h>

#define BB 8
#define NN 2048
#define DD 128
#define TI 64

typedef unsigned long long u64;
typedef unsigned int u32;
typedef unsigned short u16;

// -------- scratch --------
__device__ __align__(128) u16 g_Wh_hi[BB * NN * DD];  // [b][n][d] bf16 hi plane
__device__ __align__(128) u16 g_Wh_lo[BB * NN * DD];  // lo plane
__device__ float g_e1[BB * NN];
__device__ float g_e2[BB * NN];
__device__ float g_pooled[BB * DD];

// -------- helpers --------
__device__ __forceinline__ u64 pack2(float x, float y) {
    u64 r; asm("mov.b64 %0, {%1,%2};" : "=l"(r) : "f"(x), "f"(y)); return r;
}
__device__ __forceinline__ u64 fma2(u64 a, u64 b, u64 c) {
    u64 d; asm("fma.rn.f32x2 %0, %1, %2, %3;" : "=l"(d) : "l"(a), "l"(b), "l"(c)); return d;
}
__device__ __forceinline__ float2 unpack2(u64 v) {
    float2 r; asm("mov.b64 {%0,%1}, %2;" : "=f"(r.x), "=f"(r.y) : "l"(v)); return r;
}
__device__ __forceinline__ float lrelu(float x) { return x >= 0.f ? x : 0.02f * x; }
__device__ __forceinline__ u16 f2bf(float x) { u16 r; asm("cvt.rn.bf16.f32 %0, %1;" : "=h"(r) : "f"(x)); return r; }
__device__ __forceinline__ float bf2f(u16 b) { return __uint_as_float(((u32)b) << 16); }
// packed bf16x2: low half <- a, high half <- b
__device__ __forceinline__ u32 cvt2bf(float a, float b) {
    u32 r; asm("cvt.rn.bf16x2.f32 %0, %1, %2;" : "=r"(r) : "f"(b), "f"(a)); return r;
}
__device__ __forceinline__ u32 smem_u32(const void* p) {
    u32 a; asm("{ .reg .u64 t; cvta.to.shared.u64 t, %1; cvt.u32.u64 %0, t; }" : "=r"(a) : "l"(p)); return a;
}
__device__ __forceinline__ void ldsm_x4(u32* r, u32 addr) {
    asm volatile("ldmatrix.sync.aligned.m8n8.x4.shared.b16 {%0,%1,%2,%3}, [%4];"
        : "=r"(r[0]), "=r"(r[1]), "=r"(r[2]), "=r"(r[3]) : "r"(addr));
}
__device__ __forceinline__ void ldsm_x4_t(u32* r, u32 addr) {
    asm volatile("ldmatrix.sync.aligned.m8n8.x4.trans.shared.b16 {%0,%1,%2,%3}, [%4];"
        : "=r"(r[0]), "=r"(r[1]), "=r"(r[2]), "=r"(r[3]) : "r"(addr));
}
__device__ __forceinline__ void mma_bf16(float* c, const u32* a, u32 b0, u32 b1) {
    asm volatile("mma.sync.aligned.m16n8k16.row.col.f32.bf16.bf16.f32 "
        "{%0,%1,%2,%3}, {%4,%5,%6,%7}, {%8,%9}, {%0,%1,%2,%3};"
        : "+f"(c[0]), "+f"(c[1]), "+f"(c[2]), "+f"(c[3])
        : "r"(a[0]), "r"(a[1]), "r"(a[2]), "r"(a[3]), "r"(b0), "r"(b1));
}

// ============================================================
// Kernel 0: init pooled to -inf
// ============================================================
__global__ void init_pooled_kernel() {
    int t = blockIdx.x * blockDim.x + threadIdx.x;
    if (t < BB * DD) g_pooled[t] = __int_as_float(0xff800000);
}

// ============================================================
// Kernel 1: fc1 + LN + lrelu + Wg GEMM + e1/e2 + bf16 hi/lo Wh planes
// ============================================================
__global__ void __launch_bounds__(256, 2) fc_kernel(
    const float* __restrict__ h, const float* __restrict__ W1, const float* __restrict__ b1,
    const float* __restrict__ Wg, const float* __restrict__ bg,
    const float* __restrict__ a1, const float* __restrict__ a2)
{
    extern __shared__ float sm[];
    float* Wgs = sm;                    // [128][132]
    float* x_s = Wgs + 128 * 132;       // [64][128]
    float* W1t = x_s + TI * DD;         // [10][128]
    float* h_s = W1t + 1280;            // [64][10]
    float* b1s = h_s + TI * 10;
    float* bgs = b1s + 128;
    float* a1s = bgs + 128;
    float* a2s = a1s + 128;

    int tid = threadIdx.x;
    int warp = tid >> 5, lane = tid & 31;
    int node0 = blockIdx.x * TI;

    #pragma unroll
    for (int it = 0; it < 64; it++) {
        int idx = it * 256 + tid;
        Wgs[(idx & 127) * 132 + (idx >> 7)] = Wg[idx];
    }
    for (int idx = tid; idx < 1280; idx += 256)
        W1t[(idx % 10) * 128 + (idx / 10)] = W1[idx];
    for (int idx = tid; idx < TI * 10; idx += 256)
        h_s[idx] = h[node0 * 10 + idx];
    if (tid < 128) { b1s[tid] = b1[tid]; bgs[tid] = bg[tid]; a1s[tid] = a1[tid]; a2s[tid] = a2[tid]; }
    __syncthreads();

    for (int it = 0; it < 8; it++) {
        int nl = it * 8 + warp;
        float xv[4];
        #pragma unroll
        for (int c = 0; c < 4; c++) xv[c] = b1s[4 * lane + c];
        #pragma unroll
        for (int f = 0; f < 10; f++) {
            float hf = h_s[nl * 10 + f];
            #pragma unroll
            for (int c = 0; c < 4; c++) xv[c] += hf * W1t[f * 128 + 4 * lane + c];
        }
        float s  = xv[0] + xv[1] + xv[2] + xv[3];
        float ss = xv[0]*xv[0] + xv[1]*xv[1] + xv[2]*xv[2] + xv[3]*xv[3];
        #pragma unroll
        for (int o = 16; o > 0; o >>= 1) {
            s  += __shfl_xor_sync(0xffffffffu, s, o);
            ss += __shfl_xor_sync(0xffffffffu, ss, o);
        }
        float m   = s * (1.f / 128.f);
        float var = ss * (1.f / 128.f) - m * m;
        float inv = rsqrtf(var + 1e-5f);
        #pragma unroll
        for (int c = 0; c < 4; c++)
            x_s[nl * DD + 4 * lane + c] = lrelu((xv[c] - m) * inv);
    }
    __syncthreads();

    u64 acc[8][2];
    #pragma unroll
    for (int r = 0; r < 8; r++) { acc[r][0] = 0ull; acc[r][1] = 0ull; }
    for (int kb = 0; kb < 32; kb++) {
        ulonglong2 v[4];
        #pragma unroll
        for (int q = 0; q < 4; q++)
            v[q] = *(const ulonglong2*)(Wgs + (4 * kb + q) * 132 + 4 * lane);
        #pragma unroll
        for (int r = 0; r < 8; r++) {
            float4 w4 = *(const float4*)(x_s + (warp * 8 + r) * DD + 4 * kb);
            u64 w;
            w = pack2(w4.x, w4.x); acc[r][0] = fma2(w, v[0].x, acc[r][0]); acc[r][1] = fma2(w, v[0].y, acc[r][1]);
            w = pack2(w4.y, w4.y); acc[r][0] = fma2(w, v[1].x, acc[r][0]); acc[r][1] = fma2(w, v[1].y, acc[r][1]);
            w = pack2(w4.z, w4.z); acc[r][0] = fma2(w, v[2].x, acc[r][0]); acc[r][1] = fma2(w, v[2].y, acc[r][1]);
            w = pack2(w4.w, w4.w); acc[r][0] = fma2(w, v[3].x, acc[r][0]); acc[r][1] = fma2(w, v[3].y, acc[r][1]);
        }
    }

    // epilogue: +bg, e1/e2, bf16 hi/lo planes [b][n][d]
    #pragma unroll
    for (int r = 0; r < 8; r++) {
        int gn = node0 + warp * 8 + r;
        float2 p0 = unpack2(acc[r][0]);
        float2 p1 = unpack2(acc[r][1]);
        float wv[4];
        wv[0] = p0.x + bgs[4 * lane + 0];
        wv[1] = p0.y + bgs[4 * lane + 1];
        wv[2] = p1.x + bgs[4 * lane + 2];
        wv[3] = p1.y + bgs[4 * lane + 3];
        float d1 = wv[0]*a1s[4*lane] + wv[1]*a1s[4*lane+1] + wv[2]*a1s[4*lane+2] + wv[3]*a1s[4*lane+3];
        float d2 = wv[0]*a2s[4*lane] + wv[1]*a2s[4*lane+1] + wv[2]*a2s[4*lane+2] + wv[3]*a2s[4*lane+3];
        #pragma unroll
        for (int o = 16; o > 0; o >>= 1) {
            d1 += __shfl_xor_sync(0xffffffffu, d1, o);
            d2 += __shfl_xor_sync(0xffffffffu, d2, o);
        }
        if (lane == 0) { g_e1[gn] = d1; g_e2[gn] = d2; }

        u16 hi[4], lo[4];
        #pragma unroll
        for (int c = 0; c < 4; c++) {
            hi[c] = f2bf(wv[c]);
            lo[c] = f2bf(wv[c] - bf2f(hi[c]));
        }
        u64 hp = (u64)hi[0] | ((u64)hi[1] << 16) | ((u64)hi[2] << 32) | ((u64)hi[3] << 48);
        u64 lp = (u64)lo[0] | ((u64)lo[1] << 16) | ((u64)lo[2] << 32) | ((u64)lo[3] << 48);
        *(u64*)(g_Wh_hi + (size_t)gn * DD + 4 * lane) = hp;
        *(u64*)(g_Wh_lo + (size_t)gn * DD + 4 * lane) = lp;
    }
}

// ============================================================
// Kernel 2: attention via mma.sync bf16 split (3 passes), reg accum
//   grid (16, 8) x 256 threads (8 warps). CTA: 128 i x 128 d, K-loop 16x128.
// ============================================================
#define BSTRIDE 272               /* 136 bf16 per row */
#define SM_WH_HI  0
#define SM_WH_LO  34816
#define SM_P_HI   69632
#define SM_P_LO   104448
#define SM_Z      139264
#define SM_E2     139776
#define SM_E1     140288
#define SM_TOTAL  140800
#define SM_HP     0               /* epilogue overlay [128][132] f32 */

__global__ void __launch_bounds__(256, 1) attn_kernel(const int* __restrict__ adj)
{
    extern __shared__ char smc[];
    u32 sb = smem_u32(smc);

    int tid = threadIdx.x;
    int warp = tid >> 5, lane = tid & 31;
    int b  = blockIdx.y;
    int i0 = blockIdx.x * 128;

    if (tid < 128) {
        *(float*)(smc + SM_E1 + 4 * tid) = g_e1[b * NN + i0 + tid];
    }

    float acc[64];
    #pragma unroll
    for (int q = 0; q < 64; q++) acc[q] = 0.f;
    float zp[16];
    #pragma unroll
    for (int rr = 0; rr < 16; rr++) zp[rr] = 0.f;

    const int* adjb = adj + (size_t)b * NN * NN;

    // ldmatrix address components
    const u32 aOffBase = (u32)(warp * 16 + (lane & 15)) * BSTRIDE + (u32)((lane >> 4) << 3) * 2;
    const u32 bRowOff  = (u32)(lane & 15) * BSTRIDE;
    const u32 bColOff  = (u32)((lane >> 4) << 3) * 2;
    __syncthreads();

    for (int t = 0; t < 16; t++) {
        int j0 = t * 128;
        __syncthreads();   // previous tile's reads complete

        if (tid < 128) *(float*)(smc + SM_E2 + 4 * tid) = g_e2[b * NN + j0 + tid];

        // Wh hi/lo tiles: [j 128][d 128] bf16, row stride 272B
        #pragma unroll
        for (int it = 0; it < 8; it++) {
            int c = it * 256 + tid;          // 2048 chunks of 8 bf16
            int row = c >> 4, col8 = (c & 15) << 3;
            size_t gsrc = ((size_t)(b * NN + j0 + row)) * DD + col8;
            u32 dst = (u32)row * BSTRIDE + (u32)col8 * 2;
            *(uint4*)(smc + SM_WH_HI + dst) = *(const uint4*)(g_Wh_hi + gsrc);
            *(uint4*)(smc + SM_WH_LO + dst) = *(const uint4*)(g_Wh_lo + gsrc);
        }

        // w-gen: P[i][j] hi/lo bf16 into smem (rows warp*16..+15, cols 4*lane..+3)
        #pragma unroll
        for (int rr = 0; rr < 16; rr++) {
            int il = warp * 16 + rr;
            float e1v = *(const float*)(smc + SM_E1 + 4 * il);
            int4 a4 = *(const int4*)(adjb + (size_t)(i0 + il) * NN + j0 + 4 * lane);
            float e20 = *(const float*)(smc + SM_E2 + 16 * lane + 0);
            float e21 = *(const float*)(smc + SM_E2 + 16 * lane + 4);
            float e22 = *(const float*)(smc + SM_E2 + 16 * lane + 8);
            float e23 = *(const float*)(smc + SM_E2 + 16 * lane + 12);
            float w0 = (a4.x != 0) ? __expf(lrelu(e1v + e20)) : 0.f;
            float w1 = (a4.y != 0) ? __expf(lrelu(e1v + e21)) : 0.f;
            float w2 = (a4.z != 0) ? __expf(lrelu(e1v + e22)) : 0.f;
            float w3 = (a4.w != 0) ? __expf(lrelu(e1v + e23)) : 0.f;
            zp[rr] += (w0 + w1) + (w2 + w3);
            u32 hiA = cvt2bf(w0, w1), hiB = cvt2bf(w2, w3);
            u32 loA = cvt2bf(w0 - __uint_as_float(hiA << 16), w1 - __uint_as_float(hiA & 0xffff0000u));
            u32 loB = cvt2bf(w2 - __uint_as_float(hiB << 16), w3 - __uint_as_float(hiB & 0xffff0000u));
            u32 off = (u32)il * BSTRIDE + (u32)lane * 8;
            *(u64*)(smc + SM_P_HI + off) = (u64)hiA | ((u64)hiB << 32);
            *(u64*)(smc + SM_P_LO + off) = (u64)loA | ((u64)loB << 32);
        }
        __syncthreads();

        // 3 split passes of m16n8k16 mma
        #pragma unroll
        for (int pass = 0; pass < 3; pass++) {
            u32 pA = (pass == 2) ? (sb + SM_P_LO)  : (sb + SM_P_HI);
            u32 pB = (pass == 1) ? (sb + SM_WH_LO) : (sb + SM_WH_HI);
            #pragma unroll
            for (int kk = 0; kk < 8; kk++) {
                u32 afr[4];
                ldsm_x4(afr, pA + aOffBase + (u32)kk * 32);
                #pragma unroll
                for (int nb = 0; nb < 8; nb++) {
                    u32 bfr[4];
                    ldsm_x4_t(bfr, pB + (u32)(kk * 16) * BSTRIDE + bRowOff + (u32)(nb * 16) * 2 + bColOff);
                    mma_bf16(acc + (2 * nb) * 4,     afr, bfr[0], bfr[1]);
                    mma_bf16(acc + (2 * nb + 1) * 4, afr, bfr[2], bfr[3]);
                }
            }
        }
    }

    // z: cross-lane reduce, stash per-row
    #pragma unroll
    for (int rr = 0; rr < 16; rr++) {
        float v = zp[rr];
        #pragma unroll
        for (int o = 16; o > 0; o >>= 1) v += __shfl_xor_sync(0xffffffffu, v, o);
        if (lane == 0) *(float*)(smc + SM_Z + 4 * (warp * 16 + rr)) = v;
    }
    __syncthreads();

    // epilogue: fragment rows rA = warp*16 + lane>>2, rB = rA + 8
    int rA = warp * 16 + (lane >> 2);
    int rB = rA + 8;
    float izA = 1.f / *(const float*)(smc + SM_Z + 4 * rA);
    float izB = 1.f / *(const float*)(smc + SM_Z + 4 * rB);
    float sA = 0.f, ssA = 0.f, sB = 0.f, ssB = 0.f;
    #pragma unroll
    for (int n8 = 0; n8 < 16; n8++) {
        float x0 = acc[n8 * 4 + 0] * izA, x1 = acc[n8 * 4 + 1] * izA;
        float y0 = acc[n8 * 4 + 2] * izB, y1 = acc[n8 * 4 + 3] * izB;
        acc[n8 * 4 + 0] = x0; acc[n8 * 4 + 1] = x1;
        acc[n8 * 4 + 2] = y0; acc[n8 * 4 + 3] = y1;
        sA += x0 + x1; ssA += x0 * x0 + x1 * x1;
        sB += y0 + y1; ssB += y0 * y0 + y1 * y1;
    }
    #pragma unroll
    for (int o = 1; o <= 2; o <<= 1) {
        sA  += __shfl_xor_sync(0xffffffffu, sA, o);
        ssA += __shfl_xor_sync(0xffffffffu, ssA, o);
        sB  += __shfl_xor_sync(0xffffffffu, sB, o);
        ssB += __shfl_xor_sync(0xffffffffu, ssB, o);
    }
    float mA = sA * (1.f / 128.f), vA = ssA * (1.f / 128.f) - mA * mA, iA = rsqrtf(vA + 1e-5f);
    float mB = sB * (1.f / 128.f), vB = ssB * (1.f / 128.f) - mB * mB, iB = rsqrtf(vB + 1e-5f);

    __syncthreads();          // done reading Wh smem; overlay hp
    float* s_hp = (float*)(smc + SM_HP);   // [128][132]
    int c0 = 2 * (lane & 3);
    #pragma unroll
    for (int n8 = 0; n8 < 16; n8++) {
        int col = n8 * 8 + c0;
        s_hp[rA * 132 + col]     = lrelu((acc[n8 * 4 + 0] - mA) * iA);
        s_hp[rA * 132 + col + 1] = lrelu((acc[n8 * 4 + 1] - mA) * iA);
        s_hp[rB * 132 + col]     = lrelu((acc[n8 * 4 + 2] - mB) * iB);
        s_hp[rB * 132 + col + 1] = lrelu((acc[n8 * 4 + 3] - mB) * iB);
    }
    __syncthreads();

    if (tid < 128) {
        float v = -1e30f;
        #pragma unroll 8
        for (int i = 0; i < 128; i++) v = fmaxf(v, s_hp[i * 132 + tid]);
        if (v >= 0.f) atomicMax((int*)&g_pooled[b * DD + tid], __float_as_int(v));
        else          atomicMin((unsigned int*)&g_pooled[b * DD + tid], __float_as_uint(v));
    }
}

// ============================================================
// Kernel 3: pooled @ W2.T + b2, log_softmax
// ============================================================
__global__ void final_kernel(const float* __restrict__ W2, const float* __restrict__ b2,
                             float* __restrict__ out)
{
    int warp = threadIdx.x >> 5, lane = threadIdx.x & 31;
    if (warp < BB) {
        float o0 = 0.f, o1 = 0.f;
        #pragma unroll
        for (int c = 0; c < 4; c++) {
            float p = g_pooled[warp * DD + 4 * lane + c];
            o0 += p * W2[4 * lane + c];
            o1 += p * W2[DD + 4 * lane + c];
        }
        #pragma unroll
        for (int o = 16; o > 0; o >>= 1) {
            o0 += __shfl_xor_sync(0xffffffffu, o0, o);
            o1 += __shfl_xor_sync(0xffffffffu, o1, o);
        }
        if (lane == 0) {
            o0 += b2[0]; o1 += b2[1];
            float m = fmaxf(o0, o1);
            float l = m + logf(expf(o0 - m) + expf(o1 - m));
            out[2 * warp + 0] = o0 - l;
            out[2 * warp + 1] = o1 - l;
        }
    }
}

// ============================================================
extern "C" void kernel_launch(void* const* d_in, const int* in_sizes, int n_in,
                              void* d_out, int out_size)
{
    const float* h   = (const float*)d_in[0];
    const int*   adj = (const int*)d_in[1];
    const float* W1  = (const float*)d_in[2];
    const float* b1  = (const float*)d_in[3];
    const float* Wg  = (const float*)d_in[4];
    const float* bg  = (const float*)d_in[5];
    const float* a1  = (const float*)d_in[6];
    const float* a2  = (const float*)d_in[7];
    const float* W2  = (const float*)d_in[8];
    const float* b2  = (const float*)d_in[9];
    float* out = (float*)d_out;

    int smem_fc = (128 * 132 + TI * DD + 1280 + TI * 10 + 4 * 128) * 4;
    int smem_at = SM_TOTAL;
    cudaFuncSetAttribute(fc_kernel,   cudaFuncAttributeMaxDynamicSharedMemorySize, smem_fc);
    cudaFuncSetAttribute(attn_kernel, cudaFuncAttributeMaxDynamicSharedMemorySize, smem_at);

    init_pooled_kernel<<<1, 1024>>>();
    fc_kernel<<<BB * NN / TI, 256, smem_fc>>>(h, W1, b1, Wg, bg, a1, a2);
    attn_kernel<<<dim3(16, BB), 256, smem_at>>>(adj);
    final_kernel<<<1, 256>>>(W2, b2, out);
}

// round 6
// speedup vs baseline: 2.1658x; 1.8321x over previous
#include <cuda_runtime.h>
#include <cuda_fp16.h>
#include <math.h>

#define BB 8
#define NN 2048
#define DD 128
#define TI 64
#define CSHIFT 6.0f

typedef unsigned long long u64;
typedef unsigned int u32;
typedef unsigned short u16;

// -------- scratch --------
__device__ __align__(128) u16 g_Wh_h[BB * NN * DD];   // [b][n][d] fp16 Wh
__device__ float g_e1[BB * NN];
__device__ float g_e2[BB * NN];
__device__ float g_pooled[BB * DD];

// -------- helpers --------
__device__ __forceinline__ u64 pack2(float x, float y) {
    u64 r; asm("mov.b64 %0, {%1,%2};" : "=l"(r) : "f"(x), "f"(y)); return r;
}
__device__ __forceinline__ u64 fma2(u64 a, u64 b, u64 c) {
    u64 d; asm("fma.rn.f32x2 %0, %1, %2, %3;" : "=l"(d) : "l"(a), "l"(b), "l"(c)); return d;
}
__device__ __forceinline__ float2 unpack2(u64 v) {
    float2 r; asm("mov.b64 {%0,%1}, %2;" : "=f"(r.x), "=f"(r.y) : "l"(v)); return r;
}
__device__ __forceinline__ float lrelu(float x) { return x >= 0.f ? x : 0.02f * x; }
__device__ __forceinline__ u32 smem_u32(const void* p) {
    u32 a; asm("{ .reg .u64 t; cvta.to.shared.u64 t, %1; cvt.u32.u64 %0, t; }" : "=r"(a) : "l"(p)); return a;
}
__device__ __forceinline__ void ldsm_x4(u32* r, u32 addr) {
    asm volatile("ldmatrix.sync.aligned.m8n8.x4.shared.b16 {%0,%1,%2,%3}, [%4];"
        : "=r"(r[0]), "=r"(r[1]), "=r"(r[2]), "=r"(r[3]) : "r"(addr));
}
__device__ __forceinline__ void ldsm_x4_t(u32* r, u32 addr) {
    asm volatile("ldmatrix.sync.aligned.m8n8.x4.trans.shared.b16 {%0,%1,%2,%3}, [%4];"
        : "=r"(r[0]), "=r"(r[1]), "=r"(r[2]), "=r"(r[3]) : "r"(addr));
}
__device__ __forceinline__ void mma_f16(float* c, const u32* a, u32 b0, u32 b1) {
    asm volatile("mma.sync.aligned.m16n8k16.row.col.f32.f16.f16.f32 "
        "{%0,%1,%2,%3}, {%4,%5,%6,%7}, {%8,%9}, {%0,%1,%2,%3};"
        : "+f"(c[0]), "+f"(c[1]), "+f"(c[2]), "+f"(c[3])
        : "r"(a[0]), "r"(a[1]), "r"(a[2]), "r"(a[3]), "r"(b0), "r"(b1));
}
__device__ __forceinline__ void cp_async16(u32 dst, const void* src) {
    asm volatile("cp.async.cg.shared.global [%0], [%1], 16;" :: "r"(dst), "l"(src) : "memory");
}
#define CP_COMMIT() asm volatile("cp.async.commit_group;" ::: "memory")
#define CP_WAIT0()  asm volatile("cp.async.wait_group 0;" ::: "memory")

// ============================================================
__global__ void init_pooled_kernel() {
    int t = blockIdx.x * blockDim.x + threadIdx.x;
    if (t < BB * DD) g_pooled[t] = __int_as_float(0xff800000);
}

// ============================================================
// Kernel 1: fc1 + LN + lrelu + Wg GEMM + e1/e2 + fp16 Wh plane
// ============================================================
__global__ void __launch_bounds__(256, 2) fc_kernel(
    const float* __restrict__ h, const float* __restrict__ W1, const float* __restrict__ b1,
    const float* __restrict__ Wg, const float* __restrict__ bg,
    const float* __restrict__ a1, const float* __restrict__ a2)
{
    extern __shared__ float sm[];
    float* Wgs = sm;                    // [128][132]
    float* x_s = Wgs + 128 * 132;       // [64][128]
    float* W1t = x_s + TI * DD;         // [10][128]
    float* h_s = W1t + 1280;            // [64][10]
    float* b1s = h_s + TI * 10;
    float* bgs = b1s + 128;
    float* a1s = bgs + 128;
    float* a2s = a1s + 128;

    int tid = threadIdx.x;
    int warp = tid >> 5, lane = tid & 31;
    int node0 = blockIdx.x * TI;

    #pragma unroll
    for (int it = 0; it < 64; it++) {
        int idx = it * 256 + tid;
        Wgs[(idx & 127) * 132 + (idx >> 7)] = Wg[idx];
    }
    for (int idx = tid; idx < 1280; idx += 256)
        W1t[(idx % 10) * 128 + (idx / 10)] = W1[idx];
    for (int idx = tid; idx < TI * 10; idx += 256)
        h_s[idx] = h[node0 * 10 + idx];
    if (tid < 128) { b1s[tid] = b1[tid]; bgs[tid] = bg[tid]; a1s[tid] = a1[tid]; a2s[tid] = a2[tid]; }
    __syncthreads();

    for (int it = 0; it < 8; it++) {
        int nl = it * 8 + warp;
        float xv[4];
        #pragma unroll
        for (int c = 0; c < 4; c++) xv[c] = b1s[4 * lane + c];
        #pragma unroll
        for (int f = 0; f < 10; f++) {
            float hf = h_s[nl * 10 + f];
            #pragma unroll
            for (int c = 0; c < 4; c++) xv[c] += hf * W1t[f * 128 + 4 * lane + c];
        }
        float s  = xv[0] + xv[1] + xv[2] + xv[3];
        float ss = xv[0]*xv[0] + xv[1]*xv[1] + xv[2]*xv[2] + xv[3]*xv[3];
        #pragma unroll
        for (int o = 16; o > 0; o >>= 1) {
            s  += __shfl_xor_sync(0xffffffffu, s, o);
            ss += __shfl_xor_sync(0xffffffffu, ss, o);
        }
        float m   = s * (1.f / 128.f);
        float var = ss * (1.f / 128.f) - m * m;
        float inv = rsqrtf(var + 1e-5f);
        #pragma unroll
        for (int c = 0; c < 4; c++)
            x_s[nl * DD + 4 * lane + c] = lrelu((xv[c] - m) * inv);
    }
    __syncthreads();

    u64 acc[8][2];
    #pragma unroll
    for (int r = 0; r < 8; r++) { acc[r][0] = 0ull; acc[r][1] = 0ull; }
    for (int kb = 0; kb < 32; kb++) {
        ulonglong2 v[4];
        #pragma unroll
        for (int q = 0; q < 4; q++)
            v[q] = *(const ulonglong2*)(Wgs + (4 * kb + q) * 132 + 4 * lane);
        #pragma unroll
        for (int r = 0; r < 8; r++) {
            float4 w4 = *(const float4*)(x_s + (warp * 8 + r) * DD + 4 * kb);
            u64 w;
            w = pack2(w4.x, w4.x); acc[r][0] = fma2(w, v[0].x, acc[r][0]); acc[r][1] = fma2(w, v[0].y, acc[r][1]);
            w = pack2(w4.y, w4.y); acc[r][0] = fma2(w, v[1].x, acc[r][0]); acc[r][1] = fma2(w, v[1].y, acc[r][1]);
            w = pack2(w4.z, w4.z); acc[r][0] = fma2(w, v[2].x, acc[r][0]); acc[r][1] = fma2(w, v[2].y, acc[r][1]);
            w = pack2(w4.w, w4.w); acc[r][0] = fma2(w, v[3].x, acc[r][0]); acc[r][1] = fma2(w, v[3].y, acc[r][1]);
        }
    }

    #pragma unroll
    for (int r = 0; r < 8; r++) {
        int gn = node0 + warp * 8 + r;
        float2 p0 = unpack2(acc[r][0]);
        float2 p1 = unpack2(acc[r][1]);
        float wv[4];
        wv[0] = p0.x + bgs[4 * lane + 0];
        wv[1] = p0.y + bgs[4 * lane + 1];
        wv[2] = p1.x + bgs[4 * lane + 2];
        wv[3] = p1.y + bgs[4 * lane + 3];
        float d1 = wv[0]*a1s[4*lane] + wv[1]*a1s[4*lane+1] + wv[2]*a1s[4*lane+2] + wv[3]*a1s[4*lane+3];
        float d2 = wv[0]*a2s[4*lane] + wv[1]*a2s[4*lane+1] + wv[2]*a2s[4*lane+2] + wv[3]*a2s[4*lane+3];
        #pragma unroll
        for (int o = 16; o > 0; o >>= 1) {
            d1 += __shfl_xor_sync(0xffffffffu, d1, o);
            d2 += __shfl_xor_sync(0xffffffffu, d2, o);
        }
        if (lane == 0) { g_e1[gn] = d1; g_e2[gn] = d2; }

        u16 hv[4];
        #pragma unroll
        for (int c = 0; c < 4; c++) hv[c] = __half_as_ushort(__float2half_rn(wv[c]));
        u64 hp = (u64)hv[0] | ((u64)hv[1] << 16) | ((u64)hv[2] << 32) | ((u64)hv[3] << 48);
        *(u64*)(g_Wh_h + (size_t)gn * DD + 4 * lane) = hp;
    }
}

// ============================================================
// Kernel 2: attention, single-pass fp16 mma, cp.async pipelined
//   grid (16, 8) x 256 threads (8 warps). CTA: 128 i x 2048 j.
// ============================================================
#define BSTRIDE 272
#define SM_WH0  0
#define SM_WH1  34816
#define SM_P    69632
#define SM_E2   104448      /* 2048 f32 = 8192B */
#define SM_Z    112640
#define SM_TOTAL 113152
#define SM_HP   0           /* epilogue overlay [128][132] f32 */

__global__ void __launch_bounds__(256, 1) attn_kernel(const int* __restrict__ adj)
{
    extern __shared__ char smc[];
    u32 sb = smem_u32(smc);

    int tid = threadIdx.x;
    int warp = tid >> 5, lane = tid & 31;
    int b  = blockIdx.y;
    int i0 = blockIdx.x * 128;

    // e2 (whole row of 2048) to smem once
    #pragma unroll
    for (int q = 0; q < 8; q++)
        *(float*)(smc + SM_E2 + 4 * (q * 256 + tid)) = g_e2[b * NN + q * 256 + tid];

    float e1r[16];
    #pragma unroll
    for (int rr = 0; rr < 16; rr++) e1r[rr] = g_e1[b * NN + i0 + warp * 16 + rr];

    float acc[64];
    #pragma unroll
    for (int q = 0; q < 64; q++) acc[q] = 0.f;
    float zp[16];
    #pragma unroll
    for (int rr = 0; rr < 16; rr++) zp[rr] = 0.f;

    const int* adjb = adj + (size_t)b * NN * NN;
    const u16* Whb  = g_Wh_h + (size_t)b * NN * DD;

    const u32 aOffBase = (u32)(warp * 16 + (lane & 15)) * BSTRIDE + (u32)(((lane >> 4) << 3) * 2);
    const u32 bRowOff  = (u32)(lane & 15) * BSTRIDE;
    const u32 bColOff  = (u32)(((lane >> 4) << 3) * 2);
    // cp.async chunk mapping: chunk c -> row c>>4, col8 (c&15)<<3
    const int cpRow0 = tid >> 4;              // rows tid>>4, +16 per it? (c = it*256+tid)
    const int cpCol8 = (tid & 15) << 3;

    // prologue: Wh tile 0 + adj tile 0
    {
        #pragma unroll
        for (int it = 0; it < 8; it++) {
            int row = it * 16 + cpRow0;
            cp_async16(sb + SM_WH0 + (u32)row * BSTRIDE + (u32)cpCol8 * 2,
                       Whb + (size_t)row * DD + cpCol8);
        }
        CP_COMMIT();
    }
    int4 a4[16];
    #pragma unroll
    for (int rr = 0; rr < 16; rr++)
        a4[rr] = *(const int4*)(adjb + (size_t)(i0 + warp * 16 + rr) * NN + 4 * lane);
    __syncthreads();   // e2 visible

    for (int t = 0; t < 16; t++) {
        int j0 = t * 128;
        u32 pW = sb + ((t & 1) ? SM_WH1 : SM_WH0);

        // ---- w-gen (P rows are warp-private) ----
        __syncwarp();   // order vs own prior LDSM reads of P
        float4 e2v = *(const float4*)(smc + SM_E2 + j0 * 4 + 16 * lane);
        #pragma unroll
        for (int rr = 0; rr < 16; rr++) {
            int il = warp * 16 + rr;
            float w0 = (a4[rr].x != 0) ? __expf(lrelu(e1r[rr] + e2v.x) - CSHIFT) : 0.f;
            float w1 = (a4[rr].y != 0) ? __expf(lrelu(e1r[rr] + e2v.y) - CSHIFT) : 0.f;
            float w2 = (a4[rr].z != 0) ? __expf(lrelu(e1r[rr] + e2v.z) - CSHIFT) : 0.f;
            float w3 = (a4[rr].w != 0) ? __expf(lrelu(e1r[rr] + e2v.w) - CSHIFT) : 0.f;
            zp[rr] += (w0 + w1) + (w2 + w3);
            __half2 h01 = __floats2half2_rn(w0, w1);
            __half2 h23 = __floats2half2_rn(w2, w3);
            uint2 pk;
            pk.x = *(u32*)&h01; pk.y = *(u32*)&h23;
            *(uint2*)(smc + SM_P + (u32)il * BSTRIDE + (u32)lane * 8) = pk;
        }

        // ---- wait Wh[t], make visible ----
        CP_WAIT0();
        __syncthreads();

        // ---- prefetch tile t+1: Wh via cp.async, adj to regs ----
        if (t < 15) {
            int j1 = j0 + 128;
            u32 pWn = sb + ((t & 1) ? SM_WH0 : SM_WH1);
            #pragma unroll
            for (int it = 0; it < 8; it++) {
                int row = it * 16 + cpRow0;
                cp_async16(pWn + (u32)row * BSTRIDE + (u32)cpCol8 * 2,
                           Whb + (size_t)(j1 + row) * DD + cpCol8);
            }
            CP_COMMIT();
            #pragma unroll
            for (int rr = 0; rr < 16; rr++)
                a4[rr] = *(const int4*)(adjb + (size_t)(i0 + warp * 16 + rr) * NN + j1 + 4 * lane);
        }

        // ---- single-pass fp16 MMA ----
        u32 pP = sb + SM_P;
        #pragma unroll
        for (int kk = 0; kk < 8; kk++) {
            u32 afr[4];
            ldsm_x4(afr, pP + aOffBase + (u32)kk * 32);
            #pragma unroll
            for (int nb = 0; nb < 8; nb++) {
                u32 bfr[4];
                ldsm_x4_t(bfr, pW + (u32)(kk * 16) * BSTRIDE + bRowOff + (u32)(nb * 32) + bColOff);
                mma_f16(acc + (2 * nb) * 4,     afr, bfr[0], bfr[1]);
                mma_f16(acc + (2 * nb + 1) * 4, afr, bfr[2], bfr[3]);
            }
        }
    }

    // ---- z reduce ----
    #pragma unroll
    for (int rr = 0; rr < 16; rr++) {
        float v = zp[rr];
        #pragma unroll
        for (int o = 16; o > 0; o >>= 1) v += __shfl_xor_sync(0xffffffffu, v, o);
        if (lane == 0) *(float*)(smc + SM_Z + 4 * (warp * 16 + rr)) = v;
    }
    __syncthreads();

    // ---- epilogue: /Z, LN, lrelu ----
    int rA = warp * 16 + (lane >> 2);
    int rB = rA + 8;
    float izA = 1.f / *(const float*)(smc + SM_Z + 4 * rA);
    float izB = 1.f / *(const float*)(smc + SM_Z + 4 * rB);
    float sA = 0.f, ssA = 0.f, sB = 0.f, ssB = 0.f;
    #pragma unroll
    for (int n8 = 0; n8 < 16; n8++) {
        float x0 = acc[n8 * 4 + 0] * izA, x1 = acc[n8 * 4 + 1] * izA;
        float y0 = acc[n8 * 4 + 2] * izB, y1 = acc[n8 * 4 + 3] * izB;
        acc[n8 * 4 + 0] = x0; acc[n8 * 4 + 1] = x1;
        acc[n8 * 4 + 2] = y0; acc[n8 * 4 + 3] = y1;
        sA += x0 + x1; ssA += x0 * x0 + x1 * x1;
        sB += y0 + y1; ssB += y0 * y0 + y1 * y1;
    }
    #pragma unroll
    for (int o = 1; o <= 2; o <<= 1) {
        sA  += __shfl_xor_sync(0xffffffffu, sA, o);
        ssA += __shfl_xor_sync(0xffffffffu, ssA, o);
        sB  += __shfl_xor_sync(0xffffffffu, sB, o);
        ssB += __shfl_xor_sync(0xffffffffu, ssB, o);
    }
    float mA = sA * (1.f / 128.f), vA = ssA * (1.f / 128.f) - mA * mA, iA = rsqrtf(vA + 1e-5f);
    float mB = sB * (1.f / 128.f), vB = ssB * (1.f / 128.f) - mB * mB, iB = rsqrtf(vB + 1e-5f);

    __syncthreads();
    float* s_hp = (float*)(smc + SM_HP);   // [128][132]
    int c0 = 2 * (lane & 3);
    #pragma unroll
    for (int n8 = 0; n8 < 16; n8++) {
        int col = n8 * 8 + c0;
        s_hp[rA * 132 + col]     = lrelu((acc[n8 * 4 + 0] - mA) * iA);
        s_hp[rA * 132 + col + 1] = lrelu((acc[n8 * 4 + 1] - mA) * iA);
        s_hp[rB * 132 + col]     = lrelu((acc[n8 * 4 + 2] - mB) * iB);
        s_hp[rB * 132 + col + 1] = lrelu((acc[n8 * 4 + 3] - mB) * iB);
    }
    __syncthreads();

    if (tid < 128) {
        float v = -1e30f;
        #pragma unroll 8
        for (int i = 0; i < 128; i++) v = fmaxf(v, s_hp[i * 132 + tid]);
        if (v >= 0.f) atomicMax((int*)&g_pooled[b * DD + tid], __float_as_int(v));
        else          atomicMin((unsigned int*)&g_pooled[b * DD + tid], __float_as_uint(v));
    }
}

// ============================================================
__global__ void final_kernel(const float* __restrict__ W2, const float* __restrict__ b2,
                             float* __restrict__ out)
{
    int warp = threadIdx.x >> 5, lane = threadIdx.x & 31;
    if (warp < BB) {
        float o0 = 0.f, o1 = 0.f;
        #pragma unroll
        for (int c = 0; c < 4; c++) {
            float p = g_pooled[warp * DD + 4 * lane + c];
            o0 += p * W2[4 * lane + c];
            o1 += p * W2[DD + 4 * lane + c];
        }
        #pragma unroll
        for (int o = 16; o > 0; o >>= 1) {
            o0 += __shfl_xor_sync(0xffffffffu, o0, o);
            o1 += __shfl_xor_sync(0xffffffffu, o1, o);
        }
        if (lane == 0) {
            o0 += b2[0]; o1 += b2[1];
            float m = fmaxf(o0, o1);
            float l = m + logf(expf(o0 - m) + expf(o1 - m));
            out[2 * warp + 0] = o0 - l;
            out[2 * warp + 1] = o1 - l;
        }
    }
}

// ============================================================
extern "C" void kernel_launch(void* const* d_in, const int* in_sizes, int n_in,
                              void* d_out, int out_size)
{
    const float* h   = (const float*)d_in[0];
    const int*   adj = (const int*)d_in[1];
    const float* W1  = (const float*)d_in[2];
    const float* b1  = (const float*)d_in[3];
    const float* Wg  = (const float*)d_in[4];
    const float* bg  = (const float*)d_in[5];
    const float* a1  = (const float*)d_in[6];
    const float* a2  = (const float*)d_in[7];
    const float* W2  = (const float*)d_in[8];
    const float* b2  = (const float*)d_in[9];
    float* out = (float*)d_out;

    int smem_fc = (128 * 132 + TI * DD + 1280 + TI * 10 + 4 * 128) * 4;
    int smem_at = SM_TOTAL;
    cudaFuncSetAttribute(fc_kernel,   cudaFuncAttributeMaxDynamicSharedMemorySize, smem_fc);
    cudaFuncSetAttribute(attn_kernel, cudaFuncAttributeMaxDynamicSharedMemorySize, smem_at);

    init_pooled_kernel<<<1, 1024>>>();
    fc_kernel<<<BB * NN / TI, 256, smem_fc>>>(h, W1, b1, Wg, bg, a1, a2);
    attn_kernel<<<dim3(16, BB), 256, smem_at>>>(adj);
    final_kernel<<<1, 256>>>(W2, b2, out);
}